// round 1
// baseline (speedup 1.0000x reference)
#include <cuda_runtime.h>

#define N 128
#define N2 (N*N)
#define N3 (N*N*N)

static constexpr int S64 = 64*64*64;
static constexpr int S32 = 32*32*32;
static constexpr int S16 = 16*16*16;
static constexpr int S8  = 8*8*8;
static constexpr int S4  = 4*4*4;
static constexpr int S2  = 2*2*2;

static constexpr size_t O_U   = 0;
static constexpr size_t O_V   = (size_t)1*N3;
static constexpr size_t O_W   = (size_t)2*N3;
static constexpr size_t O_BU  = (size_t)3*N3;
static constexpr size_t O_BV  = (size_t)4*N3;
static constexpr size_t O_BW  = (size_t)5*N3;
static constexpr size_t O_B   = (size_t)6*N3;
static constexpr size_t O_R0  = (size_t)7*N3;
static constexpr size_t O_R1  = (size_t)8*N3;
static constexpr size_t O_R2  = O_R1 + S64;
static constexpr size_t O_R3  = O_R2 + S32;
static constexpr size_t O_R4  = O_R3 + S16;
static constexpr size_t O_R5  = O_R4 + S8;
static constexpr size_t O_R6  = O_R5 + S4;
static constexpr size_t O_R7  = O_R6 + S2;
static constexpr size_t O_W2  = O_R7 + 8;
static constexpr size_t O_W4  = O_W2 + S2;
static constexpr size_t O_W8  = O_W4 + S4;
static constexpr size_t O_W16 = O_W8 + S8;
static constexpr size_t O_W32 = O_W16 + S16;
static constexpr size_t O_W64 = O_W32 + S32;
static constexpr size_t SCRATCH_TOT = O_W64 + S64;

__device__ float g_scratch[SCRATCH_TOT];

struct Nb6 { float w, e, s, n, b, t; };

// edge-pad (Neumann clamp) neighbor fetch
__device__ __forceinline__ Nb6 nb_edge(const float* __restrict__ A, int id,
                                       int i, int j, int k, float c) {
    Nb6 r;
    r.w = (i > 0)     ? A[id - 1]  : c;
    r.e = (i < N - 1) ? A[id + 1]  : c;
    r.s = (j > 0)     ? A[id - N]  : c;
    r.n = (j < N - 1) ? A[id + N]  : c;
    r.b = (k > 0)     ? A[id - N2] : c;
    r.t = (k < N - 1) ? A[id + N2] : c;
    return r;
}

// bc_u: edge pad, but the -x halo face is ub = 1.0
__device__ __forceinline__ Nb6 nb_bcu(const float* __restrict__ A, int id,
                                      int i, int j, int k, float c) {
    Nb6 r = nb_edge(A, id, i, j, k, c);
    if (i == 0) r.w = 1.0f;
    return r;
}

__device__ __forceinline__ float lap6(const Nb6& m, float c) {
    return m.w + m.e + m.s + m.n + m.b + m.t - 6.0f * c;
}

// ---------------- kernels ----------------

__global__ void k_solid(const float* __restrict__ vu, const float* __restrict__ vv,
                        const float* __restrict__ vw, const float* __restrict__ sg,
                        const float* __restrict__ dtp,
                        float* __restrict__ u, float* __restrict__ v, float* __restrict__ w)
{
    int i = blockIdx.x * blockDim.x + threadIdx.x;
    int j = blockIdx.y * blockDim.y + threadIdx.y;
    int k = blockIdx.z * blockDim.z + threadIdx.z;
    int id = (k * N + j) * N + i;
    float dt = dtp[0];
    float f = 1.0f / (1.0f + dt * sg[id]);
    u[id] = vu[id] * f;
    v[id] = vv[id] * f;
    w[id] = vw[id] * f;
}

__global__ void k_predictor(const float* __restrict__ u, const float* __restrict__ v,
                            const float* __restrict__ w, const float* __restrict__ p,
                            const float* __restrict__ sg, const float* __restrict__ dtp,
                            float* __restrict__ bu, float* __restrict__ bv,
                            float* __restrict__ bw)
{
    int i = blockIdx.x * blockDim.x + threadIdx.x;
    int j = blockIdx.y * blockDim.y + threadIdx.y;
    int k = blockIdx.z * blockDim.z + threadIdx.z;
    int id = (k * N + j) * N + i;
    float dt = dtp[0];
    float uc = u[id], vc = v[id], wc = w[id], pc = p[id];
    float f = 1.0f / (1.0f + dt * sg[id]);

    Nb6 np = nb_edge(p, id, i, j, k, pc);
    float px = 0.5f * (np.e - np.w);
    float py = 0.5f * (np.n - np.s);
    float pz = 0.5f * (np.t - np.b);

    Nb6 nu = nb_bcu(u, id, i, j, k, uc);
    float lapu = lap6(nu, uc);
    float axu = 0.5f * (nu.e - nu.w), ayu = 0.5f * (nu.n - nu.s), azu = 0.5f * (nu.t - nu.b);
    bu[id] = (uc + 0.5f * dt * (lapu - uc * axu - vc * ayu - wc * azu) - dt * px) * f;

    Nb6 nv = nb_edge(v, id, i, j, k, vc);
    float lapv = lap6(nv, vc);
    float axv = 0.5f * (nv.e - nv.w), ayv = 0.5f * (nv.n - nv.s), azv = 0.5f * (nv.t - nv.b);
    bv[id] = (vc + 0.5f * dt * (lapv - uc * axv - vc * ayv - wc * azv) - dt * py) * f;

    Nb6 nw = nb_edge(w, id, i, j, k, wc);
    float lapw = lap6(nw, wc);
    float axw = 0.5f * (nw.e - nw.w), ayw = 0.5f * (nw.n - nw.s), azw = 0.5f * (nw.t - nw.b);
    bw[id] = (wc + 0.5f * dt * (lapw - uc * axw - vc * ayw - wc * azw) - dt * pz) * f;
}

__global__ void k_corrector(const float* __restrict__ bu, const float* __restrict__ bv,
                            const float* __restrict__ bw, const float* __restrict__ p,
                            const float* __restrict__ sg, const float* __restrict__ dtp,
                            float* __restrict__ u, float* __restrict__ v,
                            float* __restrict__ w)
{
    int i = blockIdx.x * blockDim.x + threadIdx.x;
    int j = blockIdx.y * blockDim.y + threadIdx.y;
    int k = blockIdx.z * blockDim.z + threadIdx.z;
    int id = (k * N + j) * N + i;
    float dt = dtp[0];
    float uc = u[id], vc = v[id], wc = w[id], pc = p[id];
    float buc = bu[id], bvc = bv[id], bwc = bw[id];
    float f = 1.0f / (1.0f + dt * sg[id]);

    Nb6 np = nb_edge(p, id, i, j, k, pc);
    float px = 0.5f * (np.e - np.w);
    float py = 0.5f * (np.n - np.s);
    float pz = 0.5f * (np.t - np.b);

    Nb6 nu = nb_bcu(bu, id, i, j, k, buc);
    float lapu = lap6(nu, buc);
    float axu = 0.5f * (nu.e - nu.w), ayu = 0.5f * (nu.n - nu.s), azu = 0.5f * (nu.t - nu.b);
    float un = (uc + dt * (lapu - buc * axu - bvc * ayu - bwc * azu) - dt * px) * f;

    Nb6 nv = nb_edge(bv, id, i, j, k, bvc);
    float lapv = lap6(nv, bvc);
    float axv = 0.5f * (nv.e - nv.w), ayv = 0.5f * (nv.n - nv.s), azv = 0.5f * (nv.t - nv.b);
    float vn = (vc + dt * (lapv - buc * axv - bvc * ayv - bwc * azv) - dt * py) * f;

    Nb6 nw = nb_edge(bw, id, i, j, k, bwc);
    float lapw = lap6(nw, bwc);
    float axw = 0.5f * (nw.e - nw.w), ayw = 0.5f * (nw.n - nw.s), azw = 0.5f * (nw.t - nw.b);
    float wn = (wc + dt * (lapw - buc * axw - bvc * ayw - bwc * azw) - dt * pz) * f;

    u[id] = un; v[id] = vn; w[id] = wn;
}

__global__ void k_div(const float* __restrict__ u, const float* __restrict__ v,
                      const float* __restrict__ w, const float* __restrict__ dtp,
                      float* __restrict__ b)
{
    int i = blockIdx.x * blockDim.x + threadIdx.x;
    int j = blockIdx.y * blockDim.y + threadIdx.y;
    int k = blockIdx.z * blockDim.z + threadIdx.z;
    int id = (k * N + j) * N + i;
    float dt = dtp[0];
    float uw = (i > 0)     ? u[id - 1]  : 1.0f;      // bc_u inlet
    float ue = (i < N - 1) ? u[id + 1]  : u[id];
    float vs = (j > 0)     ? v[id - N]  : v[id];
    float vn = (j < N - 1) ? v[id + N]  : v[id];
    float wb = (k > 0)     ? w[id - N2] : w[id];
    float wt = (k < N - 1) ? w[id + N2] : w[id];
    float div = 0.5f * (ue - uw) + 0.5f * (vn - vs) + 0.5f * (wt - wb);
    b[id] = -div / dt;
}

__global__ void k_residual(const float* __restrict__ p, const float* __restrict__ b,
                           float* __restrict__ r0)
{
    int i = blockIdx.x * blockDim.x + threadIdx.x;
    int j = blockIdx.y * blockDim.y + threadIdx.y;
    int k = blockIdx.z * blockDim.z + threadIdx.z;
    int id = (k * N + j) * N + i;
    float pc = p[id];
    Nb6 np = nb_edge(p, id, i, j, k, pc);
    r0[id] = lap6(np, pc) - b[id];
}

__global__ void k_restrict(const float* __restrict__ in, float* __restrict__ out, int s)
{
    int idx = blockIdx.x * blockDim.x + threadIdx.x;
    int n = s * s * s;
    if (idx >= n) return;
    int i = idx % s;
    int j = (idx / s) % s;
    int k = idx / (s * s);
    int t = 2 * s;
    int ib = 2 * i, jb = 2 * j, kb = 2 * k;
    const float* r0 = in + ((size_t)kb * t + jb) * t + ib;
    const float* r1 = r0 + (size_t)t * t;
    float sum = r0[0] + r0[1] + r0[t] + r0[t + 1]
              + r1[0] + r1[1] + r1[t] + r1[t + 1];
    out[idx] = 0.125f * sum;
}

// smoother (Jacobi on zero-padded wmg; center term cancels) fused with x2 prolong
__global__ void k_smoothprol(const float* __restrict__ win, const float* __restrict__ r,
                             float* __restrict__ out, int s)
{
    int idx = blockIdx.x * blockDim.x + threadIdx.x;
    int n = s * s * s;
    if (idx >= n) return;
    int i = idx % s;
    int j = (idx / s) % s;
    int k = idx / (s * s);
    float nsum = 0.0f;
    if (i > 0)     nsum += win[idx - 1];
    if (i < s - 1) nsum += win[idx + 1];
    if (j > 0)     nsum += win[idx - s];
    if (j < s - 1) nsum += win[idx + s];
    if (k > 0)     nsum += win[idx - s * s];
    if (k < s - 1) nsum += win[idx + s * s];
    float wnew = (nsum - r[idx]) * (1.0f / 6.0f);
    int t = 2 * s;
    size_t o = ((size_t)(2 * k) * t + 2 * j) * t + 2 * i;
    size_t o2 = o + (size_t)t * t;
    out[o] = wnew;      out[o + 1] = wnew;
    out[o + t] = wnew;  out[o + t + 1] = wnew;
    out[o2] = wnew;     out[o2 + 1] = wnew;
    out[o2 + t] = wnew; out[o2 + t + 1] = wnew;
}

__global__ void k_pupdate(const float* __restrict__ pin, const float* __restrict__ wmg,
                          const float* __restrict__ r0, float* __restrict__ pout)
{
    int id = blockIdx.x * blockDim.x + threadIdx.x;
    pout[id] = pin[id] - wmg[id] + r0[id] * (1.0f / 6.0f);
}

__global__ void k_final(const float* __restrict__ u, const float* __restrict__ v,
                        const float* __restrict__ w, const float* __restrict__ p,
                        const float* __restrict__ sg, const float* __restrict__ dtp,
                        float* __restrict__ ou, float* __restrict__ ov,
                        float* __restrict__ ow)
{
    int i = blockIdx.x * blockDim.x + threadIdx.x;
    int j = blockIdx.y * blockDim.y + threadIdx.y;
    int k = blockIdx.z * blockDim.z + threadIdx.z;
    int id = (k * N + j) * N + i;
    float dt = dtp[0];
    float pc = p[id];
    Nb6 np = nb_edge(p, id, i, j, k, pc);
    float px = 0.5f * (np.e - np.w);
    float py = 0.5f * (np.n - np.s);
    float pz = 0.5f * (np.t - np.b);
    float f = 1.0f / (1.0f + dt * sg[id]);
    ou[id] = (u[id] - dt * px) * f;
    ov[id] = (v[id] - dt * py) * f;
    ow[id] = (w[id] - dt * pz) * f;
}

__global__ void k_copy1(const float* __restrict__ src, float* __restrict__ dst)
{
    dst[0] = src[0];
}

// ---------------- host ----------------

static inline dim3 g1(int n) { return dim3((unsigned)((n + 255) / 256)); }

extern "C" void kernel_launch(void* const* d_in, const int* in_sizes, int n_in,
                              void* d_out, int out_size)
{
    const float* vu  = (const float*)d_in[0];
    const float* vv  = (const float*)d_in[1];
    const float* vw  = (const float*)d_in[2];
    const float* vp  = (const float*)d_in[3];
    const float* sg  = (const float*)d_in[4];
    const float* dtp = (const float*)d_in[5];

    float* out = (float*)d_out;
    float* out_u   = out;
    float* out_v   = out + (size_t)1 * N3;
    float* out_w   = out + (size_t)2 * N3;
    float* out_p   = out + (size_t)3 * N3;
    float* out_wmg = out + (size_t)4 * N3;
    float* out_r   = out + (size_t)5 * N3;

    float* SC = nullptr;
    cudaGetSymbolAddress((void**)&SC, g_scratch);

    float* U  = SC + O_U;   float* V  = SC + O_V;   float* W  = SC + O_W;
    float* BU = SC + O_BU;  float* BV = SC + O_BV;  float* BW = SC + O_BW;
    float* B  = SC + O_B;   float* R0 = SC + O_R0;
    float* R1 = SC + O_R1;  float* R2 = SC + O_R2;  float* R3 = SC + O_R3;
    float* R4 = SC + O_R4;  float* R5 = SC + O_R5;  float* R6 = SC + O_R6;
    float* R7 = SC + O_R7;
    float* W2 = SC + O_W2;  float* W4 = SC + O_W4;  float* W8 = SC + O_W8;
    float* W16 = SC + O_W16; float* W32 = SC + O_W32; float* W64 = SC + O_W64;

    dim3 TB(32, 4, 4), TG(N / 32, N / 4, N / 4);

    // momentum step
    k_solid<<<TG, TB>>>(vu, vv, vw, sg, dtp, U, V, W);
    k_predictor<<<TG, TB>>>(U, V, W, vp, sg, dtp, BU, BV, BW);
    k_corrector<<<TG, TB>>>(BU, BV, BW, vp, sg, dtp, U, V, W);
    k_div<<<TG, TB>>>(U, V, W, dtp, B);

    // multigrid F-cycle, 2 iterations
    for (int it = 0; it < 2; ++it) {
        const float* pin = (it == 0) ? vp : out_p;

        k_residual<<<TG, TB>>>(pin, B, R0);

        k_restrict<<<g1(S64), 256>>>(R0, R1, 64);
        k_restrict<<<g1(S32), 256>>>(R1, R2, 32);
        k_restrict<<<g1(S16), 256>>>(R2, R3, 16);
        k_restrict<<<g1(S8),  256>>>(R3, R4, 8);
        k_restrict<<<g1(S4),  256>>>(R4, R5, 4);
        k_restrict<<<g1(S2),  256>>>(R5, R6, 2);
        k_restrict<<<g1(1),   256>>>(R6, R7, 1);

        // s=1: all neighbor reads are guarded out; win argument is unused
        k_smoothprol<<<g1(1),   256>>>(W4,  R7, W2, 1);
        k_smoothprol<<<g1(S2),  256>>>(W2,  R6, W4, 2);
        k_smoothprol<<<g1(S4),  256>>>(W4,  R5, W8, 4);
        k_smoothprol<<<g1(S8),  256>>>(W8,  R4, W16, 8);
        k_smoothprol<<<g1(S16), 256>>>(W16, R3, W32, 16);
        k_smoothprol<<<g1(S32), 256>>>(W32, R2, W64, 32);
        k_smoothprol<<<g1(S64), 256>>>(W64, R1, out_wmg, 64);

        k_pupdate<<<N3 / 256, 256>>>(pin, out_wmg, R0, out_p);
    }

    // final projection + drag
    k_final<<<TG, TB>>>(U, V, W, out_p, sg, dtp, out_u, out_v, out_w);
    k_copy1<<<1, 1>>>(R7, out_r);
}

// round 3
// speedup vs baseline: 1.2957x; 1.2957x over previous
#include <cuda_runtime.h>

#define N 128
#define N2 (N*N)
#define N3 (N*N*N)

static constexpr int S64 = 64*64*64;
static constexpr int S32 = 32*32*32;

static constexpr size_t O_U   = 0;
static constexpr size_t O_V   = (size_t)1*N3;
static constexpr size_t O_W   = (size_t)2*N3;
static constexpr size_t O_BU  = (size_t)3*N3;
static constexpr size_t O_BV  = (size_t)4*N3;
static constexpr size_t O_BW  = (size_t)5*N3;
static constexpr size_t O_B   = (size_t)6*N3;
static constexpr size_t O_R0  = (size_t)7*N3;
static constexpr size_t O_F   = (size_t)8*N3;
static constexpr size_t O_R1  = (size_t)9*N3;
static constexpr size_t O_R2  = O_R1 + S64;
static constexpr size_t O_W32 = O_R2 + S32;
static constexpr size_t O_W64 = O_W32 + S32;
static constexpr size_t SCRATCH_TOT = O_W64 + S64;

__device__ float g_scratch[SCRATCH_TOT];

struct Nb6 { float w, e, s, n, b, t; };

__device__ __forceinline__ Nb6 nb_edge(const float* __restrict__ A, int id,
                                       int i, int j, int k, float c) {
    Nb6 r;
    r.w = (i > 0)     ? A[id - 1]  : c;
    r.e = (i < N - 1) ? A[id + 1]  : c;
    r.s = (j > 0)     ? A[id - N]  : c;
    r.n = (j < N - 1) ? A[id + N]  : c;
    r.b = (k > 0)     ? A[id - N2] : c;
    r.t = (k < N - 1) ? A[id + N2] : c;
    return r;
}

__device__ __forceinline__ Nb6 nb_bcu(const float* __restrict__ A, int id,
                                      int i, int j, int k, float c) {
    Nb6 r = nb_edge(A, id, i, j, k, c);
    if (i == 0) r.w = 1.0f;
    return r;
}

__device__ __forceinline__ float lap6(const Nb6& m, float c) {
    return m.w + m.e + m.s + m.n + m.b + m.t - 6.0f * c;
}

// ---------------- kernels ----------------

// solid-body drag: writes u,v,w AND the drag factor F (reused by 3 later kernels)
__global__ void k_solid(const float4* __restrict__ vu, const float4* __restrict__ vv,
                        const float4* __restrict__ vw, const float4* __restrict__ sg,
                        const float* __restrict__ dtp,
                        float4* __restrict__ u, float4* __restrict__ v,
                        float4* __restrict__ w, float4* __restrict__ F)
{
    int id = blockIdx.x * blockDim.x + threadIdx.x;
    float dt = dtp[0];
    float4 s = sg[id];
    float4 f;
    f.x = __fdividef(1.0f, 1.0f + dt * s.x);
    f.y = __fdividef(1.0f, 1.0f + dt * s.y);
    f.z = __fdividef(1.0f, 1.0f + dt * s.z);
    f.w = __fdividef(1.0f, 1.0f + dt * s.w);
    float4 a = vu[id]; a.x *= f.x; a.y *= f.y; a.z *= f.z; a.w *= f.w; u[id] = a;
    float4 b = vv[id]; b.x *= f.x; b.y *= f.y; b.z *= f.z; b.w *= f.w; v[id] = b;
    float4 c = vw[id]; c.x *= f.x; c.y *= f.y; c.z *= f.z; c.w *= f.w; w[id] = c;
    F[id] = f;
}

__global__ void k_predictor(const float* __restrict__ u, const float* __restrict__ v,
                            const float* __restrict__ w, const float* __restrict__ p,
                            const float* __restrict__ F, const float* __restrict__ dtp,
                            float* __restrict__ bu, float* __restrict__ bv,
                            float* __restrict__ bw)
{
    int i = blockIdx.x * blockDim.x + threadIdx.x;
    int j = blockIdx.y * blockDim.y + threadIdx.y;
    int k = blockIdx.z * blockDim.z + threadIdx.z;
    int id = (k * N + j) * N + i;
    float dt = dtp[0];
    float uc = u[id], vc = v[id], wc = w[id], pc = p[id];
    float f = F[id];

    Nb6 np = nb_edge(p, id, i, j, k, pc);
    float px = 0.5f * (np.e - np.w);
    float py = 0.5f * (np.n - np.s);
    float pz = 0.5f * (np.t - np.b);

    Nb6 nu = nb_bcu(u, id, i, j, k, uc);
    float lapu = lap6(nu, uc);
    float axu = 0.5f * (nu.e - nu.w), ayu = 0.5f * (nu.n - nu.s), azu = 0.5f * (nu.t - nu.b);
    bu[id] = (uc + 0.5f * dt * (lapu - uc * axu - vc * ayu - wc * azu) - dt * px) * f;

    Nb6 nv = nb_edge(v, id, i, j, k, vc);
    float lapv = lap6(nv, vc);
    float axv = 0.5f * (nv.e - nv.w), ayv = 0.5f * (nv.n - nv.s), azv = 0.5f * (nv.t - nv.b);
    bv[id] = (vc + 0.5f * dt * (lapv - uc * axv - vc * ayv - wc * azv) - dt * py) * f;

    Nb6 nw = nb_edge(w, id, i, j, k, wc);
    float lapw = lap6(nw, wc);
    float axw = 0.5f * (nw.e - nw.w), ayw = 0.5f * (nw.n - nw.s), azw = 0.5f * (nw.t - nw.b);
    bw[id] = (wc + 0.5f * dt * (lapw - uc * axw - vc * ayw - wc * azw) - dt * pz) * f;
}

__global__ void k_corrector(const float* __restrict__ bu, const float* __restrict__ bv,
                            const float* __restrict__ bw, const float* __restrict__ p,
                            const float* __restrict__ F, const float* __restrict__ dtp,
                            float* __restrict__ u, float* __restrict__ v,
                            float* __restrict__ w)
{
    int i = blockIdx.x * blockDim.x + threadIdx.x;
    int j = blockIdx.y * blockDim.y + threadIdx.y;
    int k = blockIdx.z * blockDim.z + threadIdx.z;
    int id = (k * N + j) * N + i;
    float dt = dtp[0];
    float uc = u[id], vc = v[id], wc = w[id], pc = p[id];
    float buc = bu[id], bvc = bv[id], bwc = bw[id];
    float f = F[id];

    Nb6 np = nb_edge(p, id, i, j, k, pc);
    float px = 0.5f * (np.e - np.w);
    float py = 0.5f * (np.n - np.s);
    float pz = 0.5f * (np.t - np.b);

    Nb6 nu = nb_bcu(bu, id, i, j, k, buc);
    float lapu = lap6(nu, buc);
    float axu = 0.5f * (nu.e - nu.w), ayu = 0.5f * (nu.n - nu.s), azu = 0.5f * (nu.t - nu.b);
    float un = (uc + dt * (lapu - buc * axu - bvc * ayu - bwc * azu) - dt * px) * f;

    Nb6 nv = nb_edge(bv, id, i, j, k, bvc);
    float lapv = lap6(nv, bvc);
    float axv = 0.5f * (nv.e - nv.w), ayv = 0.5f * (nv.n - nv.s), azv = 0.5f * (nv.t - nv.b);
    float vn = (vc + dt * (lapv - buc * axv - bvc * ayv - bwc * azv) - dt * py) * f;

    Nb6 nw = nb_edge(bw, id, i, j, k, bwc);
    float lapw = lap6(nw, bwc);
    float axw = 0.5f * (nw.e - nw.w), ayw = 0.5f * (nw.n - nw.s), azw = 0.5f * (nw.t - nw.b);
    float wn = (wc + dt * (lapw - buc * axw - bvc * ayw - bwc * azw) - dt * pz) * f;

    u[id] = un; v[id] = vn; w[id] = wn;
}

__global__ void k_div(const float* __restrict__ u, const float* __restrict__ v,
                      const float* __restrict__ w, const float* __restrict__ dtp,
                      float* __restrict__ b)
{
    int i = blockIdx.x * blockDim.x + threadIdx.x;
    int j = blockIdx.y * blockDim.y + threadIdx.y;
    int k = blockIdx.z * blockDim.z + threadIdx.z;
    int id = (k * N + j) * N + i;
    float nh = -0.5f * __fdividef(1.0f, dtp[0]);
    float uw = (i > 0)     ? u[id - 1]  : 1.0f;
    float ue = (i < N - 1) ? u[id + 1]  : u[id];
    float vs = (j > 0)     ? v[id - N]  : v[id];
    float vn = (j < N - 1) ? v[id + N]  : v[id];
    float wb = (k > 0)     ? w[id - N2] : w[id];
    float wt = (k < N - 1) ? w[id + N2] : w[id];
    b[id] = nh * ((ue - uw) + (vn - vs) + (wt - wb));
}

__global__ void k_residual(const float* __restrict__ p, const float* __restrict__ b,
                           float* __restrict__ r0)
{
    int i = blockIdx.x * blockDim.x + threadIdx.x;
    int j = blockIdx.y * blockDim.y + threadIdx.y;
    int k = blockIdx.z * blockDim.z + threadIdx.z;
    int id = (k * N + j) * N + i;
    float pc = p[id];
    Nb6 np = nb_edge(p, id, i, j, k, pc);
    r0[id] = lap6(np, pc) - b[id];
}

// two-level restrict: R0(128^3) -> R1(64^3) AND R1 -> R2(32^3) in one kernel.
// Each block: 256 threads produce an 8^3 tile of R1 (from 16^3 of R0),
// stage it in smem, then 64 threads produce the 4^3 tile of R2.
__global__ void __launch_bounds__(256)
k_restrict2(const float* __restrict__ r0, float* __restrict__ r1,
            float* __restrict__ r2)
{
    __shared__ float s1[8 * 8 * 8];
    int tid = threadIdx.x;
    // block tile origin in R1 coords (8^3 tiles over 64^3 => 8x8x8 blocks)
    int bx = blockIdx.x & 7, by = (blockIdx.x >> 3) & 7, bz = blockIdx.x >> 6;

    // phase 1: 256 threads, 2 outputs each (8^3=512)
    #pragma unroll
    for (int q = 0; q < 2; ++q) {
        int idx = tid + q * 256;
        int i = idx & 7, j = (idx >> 3) & 7, k = idx >> 6;
        int gi = bx * 8 + i, gj = by * 8 + j, gk = bz * 8 + k;   // R1 coords
        const int t = 128;
        const float* a = r0 + ((size_t)(2 * gk) * t + 2 * gj) * t + 2 * gi;
        const float* b = a + (size_t)t * t;
        float v = 0.125f * (a[0] + a[1] + a[t] + a[t + 1]
                          + b[0] + b[1] + b[t] + b[t + 1]);
        r1[((size_t)gk * 64 + gj) * 64 + gi] = v;
        s1[idx] = v;
    }
    __syncthreads();

    // phase 2: 64 threads produce 4^3 of R2 from smem
    if (tid < 64) {
        int i = tid & 3, j = (tid >> 2) & 3, k = tid >> 4;
        const int t = 8;
        const float* a = s1 + ((2 * k) * t + 2 * j) * t + 2 * i;
        const float* b = a + t * t;
        float v = 0.125f * (a[0] + a[1] + a[t] + a[t + 1]
                          + b[0] + b[1] + b[t] + b[t + 1]);
        int gi = bx * 4 + i, gj = by * 4 + j, gk = bz * 4 + k;   // R2 coords
        r2[((size_t)gk * 32 + gj) * 32 + gi] = v;
    }
}

// ---- fused MG core: all levels from 32^3 residual down to 1^3 and back up to W32 ----

__device__ __forceinline__ void restrict_stage(const float* __restrict__ src,
                                               float* __restrict__ dst,
                                               int s, int tid)
{
    int n = s * s * s;
    int t = 2 * s;
    for (int idx = tid; idx < n; idx += 1024) {
        int i = idx % s;
        int j = (idx / s) % s;
        int k = idx / (s * s);
        const float* r0 = src + ((size_t)(2 * k) * t + 2 * j) * t + 2 * i;
        const float* r1 = r0 + (size_t)t * t;
        dst[idx] = 0.125f * (r0[0] + r0[1] + r0[t] + r0[t + 1]
                           + r1[0] + r1[1] + r1[t] + r1[t + 1]);
    }
}

__device__ __forceinline__ void smooth_stage(const float* __restrict__ win,
                                             const float* __restrict__ r,
                                             float* __restrict__ out,
                                             int s, int tid, bool win_zero)
{
    int n = s * s * s;
    int t = 2 * s;
    for (int idx = tid; idx < n; idx += 1024) {
        int i = idx % s;
        int j = (idx / s) % s;
        int k = idx / (s * s);
        float nsum = 0.0f;
        if (!win_zero) {
            if (i > 0)     nsum += win[idx - 1];
            if (i < s - 1) nsum += win[idx + 1];
            if (j > 0)     nsum += win[idx - s];
            if (j < s - 1) nsum += win[idx + s];
            if (k > 0)     nsum += win[idx - s * s];
            if (k < s - 1) nsum += win[idx + s * s];
        }
        float wnew = (nsum - r[idx]) * (1.0f / 6.0f);
        size_t o = ((size_t)(2 * k) * t + 2 * j) * t + 2 * i;
        size_t o2 = o + (size_t)t * t;
        out[o] = wnew;      out[o + 1] = wnew;
        out[o + t] = wnew;  out[o + t + 1] = wnew;
        out[o2] = wnew;     out[o2 + 1] = wnew;
        out[o2 + t] = wnew; out[o2 + t + 1] = wnew;
    }
}

__global__ void __launch_bounds__(1024, 1)
k_mgcore(const float* __restrict__ R2g, float* __restrict__ W32g,
         float* __restrict__ out_r)
{
    __shared__ float sR3[4096], sR4[512], sR5[64], sR6[8], sR7[1];
    __shared__ float sW2[8], sW4[64], sW8[512], sW16[4096];
    int tid = threadIdx.x;

    restrict_stage(R2g, sR3, 16, tid); __syncthreads();
    restrict_stage(sR3, sR4, 8, tid);  __syncthreads();
    restrict_stage(sR4, sR5, 4, tid);  __syncthreads();
    restrict_stage(sR5, sR6, 2, tid);  __syncthreads();
    restrict_stage(sR6, sR7, 1, tid);  __syncthreads();
    if (tid == 0) out_r[0] = sR7[0];

    smooth_stage(nullptr, sR7, sW2, 1, tid, true);  __syncthreads();
    smooth_stage(sW2, sR6, sW4, 2, tid, false);     __syncthreads();
    smooth_stage(sW4, sR5, sW8, 4, tid, false);     __syncthreads();
    smooth_stage(sW8, sR4, sW16, 8, tid, false);    __syncthreads();
    smooth_stage(sW16, sR3, W32g, 16, tid, false);
}

// smooth+prolong grid kernel (s=32)
__global__ void k_smoothprol(const float* __restrict__ win, const float* __restrict__ r,
                             float* __restrict__ out, int s)
{
    int idx = blockIdx.x * blockDim.x + threadIdx.x;
    int n = s * s * s;
    if (idx >= n) return;
    int i = idx % s;
    int j = (idx / s) % s;
    int k = idx / (s * s);
    float nsum = 0.0f;
    if (i > 0)     nsum += win[idx - 1];
    if (i < s - 1) nsum += win[idx + 1];
    if (j > 0)     nsum += win[idx - s];
    if (j < s - 1) nsum += win[idx + s];
    if (k > 0)     nsum += win[idx - s * s];
    if (k < s - 1) nsum += win[idx + s * s];
    float wnew = (nsum - r[idx]) * (1.0f / 6.0f);
    int t = 2 * s;
    size_t o = ((size_t)(2 * k) * t + 2 * j) * t + 2 * i;
    size_t o2 = o + (size_t)t * t;
    out[o] = wnew;      out[o + 1] = wnew;
    out[o + t] = wnew;  out[o + t + 1] = wnew;
    out[o2] = wnew;     out[o2 + 1] = wnew;
    out[o2 + t] = wnew; out[o2 + t + 1] = wnew;
}

// s=64 smooth+prolong FUSED with the pressure update:
//   wmg[o8] = wnew ;  p[o8] = pin[o8] - wnew + r0[o8]/6
__global__ void k_spp64(const float* __restrict__ win, const float* __restrict__ r,
                        const float* __restrict__ pin, const float* __restrict__ r0,
                        float* __restrict__ wmg, float* __restrict__ pout)
{
    const int s = 64;
    int idx = blockIdx.x * blockDim.x + threadIdx.x;
    int i = idx % s;
    int j = (idx / s) % s;
    int k = idx / (s * s);
    float nsum = 0.0f;
    if (i > 0)     nsum += win[idx - 1];
    if (i < s - 1) nsum += win[idx + 1];
    if (j > 0)     nsum += win[idx - s];
    if (j < s - 1) nsum += win[idx + s];
    if (k > 0)     nsum += win[idx - s * s];
    if (k < s - 1) nsum += win[idx + s * s];
    float wnew = (nsum - r[idx]) * (1.0f / 6.0f);
    const int t = 2 * s;
    size_t o = ((size_t)(2 * k) * t + 2 * j) * t + 2 * i;
    #pragma unroll
    for (int dz = 0; dz < 2; ++dz)
        #pragma unroll
        for (int dy = 0; dy < 2; ++dy)
            #pragma unroll
            for (int dx = 0; dx < 2; ++dx) {
                size_t q = o + (size_t)dz * t * t + (size_t)dy * t + dx;
                wmg[q] = wnew;
                pout[q] = pin[q] - wnew + r0[q] * (1.0f / 6.0f);
            }
}

__global__ void k_final(const float* __restrict__ u, const float* __restrict__ v,
                        const float* __restrict__ w, const float* __restrict__ p,
                        const float* __restrict__ F, const float* __restrict__ dtp,
                        float* __restrict__ ou, float* __restrict__ ov,
                        float* __restrict__ ow)
{
    int i = blockIdx.x * blockDim.x + threadIdx.x;
    int j = blockIdx.y * blockDim.y + threadIdx.y;
    int k = blockIdx.z * blockDim.z + threadIdx.z;
    int id = (k * N + j) * N + i;
    float dt = dtp[0];
    float pc = p[id];
    Nb6 np = nb_edge(p, id, i, j, k, pc);
    float f = F[id];
    ou[id] = (u[id] - dt * 0.5f * (np.e - np.w)) * f;
    ov[id] = (v[id] - dt * 0.5f * (np.n - np.s)) * f;
    ow[id] = (w[id] - dt * 0.5f * (np.t - np.b)) * f;
}

// ---------------- host ----------------

static inline dim3 g1(int n) { return dim3((unsigned)((n + 255) / 256)); }

extern "C" void kernel_launch(void* const* d_in, const int* in_sizes, int n_in,
                              void* d_out, int out_size)
{
    const float* vu  = (const float*)d_in[0];
    const float* vv  = (const float*)d_in[1];
    const float* vw  = (const float*)d_in[2];
    const float* vp  = (const float*)d_in[3];
    const float* sg  = (const float*)d_in[4];
    const float* dtp = (const float*)d_in[5];

    float* out = (float*)d_out;
    float* out_u   = out;
    float* out_v   = out + (size_t)1 * N3;
    float* out_w   = out + (size_t)2 * N3;
    float* out_p   = out + (size_t)3 * N3;
    float* out_wmg = out + (size_t)4 * N3;
    float* out_r   = out + (size_t)5 * N3;

    float* SC = nullptr;
    cudaGetSymbolAddress((void**)&SC, g_scratch);

    float* U  = SC + O_U;   float* V  = SC + O_V;   float* W  = SC + O_W;
    float* BU = SC + O_BU;  float* BV = SC + O_BV;  float* BW = SC + O_BW;
    float* B  = SC + O_B;   float* R0 = SC + O_R0;  float* F  = SC + O_F;
    float* R1 = SC + O_R1;  float* R2 = SC + O_R2;
    float* W32 = SC + O_W32; float* W64 = SC + O_W64;

    dim3 TB(32, 4, 4), TG(N / 32, N / 4, N / 4);

    // momentum step
    k_solid<<<N3 / 4 / 256, 256>>>((const float4*)vu, (const float4*)vv,
                                   (const float4*)vw, (const float4*)sg, dtp,
                                   (float4*)U, (float4*)V, (float4*)W, (float4*)F);
    k_predictor<<<TG, TB>>>(U, V, W, vp, F, dtp, BU, BV, BW);
    k_corrector<<<TG, TB>>>(BU, BV, BW, vp, F, dtp, U, V, W);
    k_div<<<TG, TB>>>(U, V, W, dtp, B);

    // multigrid F-cycle, 2 iterations
    for (int it = 0; it < 2; ++it) {
        const float* pin = (it == 0) ? vp : out_p;

        k_residual<<<TG, TB>>>(pin, B, R0);
        k_restrict2<<<512, 256>>>(R0, R1, R2);
        k_mgcore<<<1, 1024>>>(R2, W32, out_r);
        k_smoothprol<<<g1(S32), 256>>>(W32, R2, W64, 32);
        k_spp64<<<g1(S64), 256>>>(W64, R1, pin, R0, out_wmg, out_p);
    }

    // final projection + drag
    k_final<<<TG, TB>>>(U, V, W, out_p, F, dtp, out_u, out_v, out_w);
}

// round 4
// speedup vs baseline: 1.6650x; 1.2850x over previous
#include <cuda_runtime.h>

#define N 128
#define N2 (N*N)
#define N3 (N*N*N)

static constexpr int S64 = 64*64*64;
static constexpr int S32 = 32*32*32;

static constexpr size_t O_U   = 0;
static constexpr size_t O_V   = (size_t)1*N3;
static constexpr size_t O_W   = (size_t)2*N3;
static constexpr size_t O_BU  = (size_t)3*N3;
static constexpr size_t O_BV  = (size_t)4*N3;
static constexpr size_t O_BW  = (size_t)5*N3;
static constexpr size_t O_B   = (size_t)6*N3;
static constexpr size_t O_R0  = (size_t)7*N3;
static constexpr size_t O_F   = (size_t)8*N3;
static constexpr size_t O_R1  = (size_t)9*N3;
static constexpr size_t O_R2  = O_R1 + S64;
static constexpr size_t O_W32 = O_R2 + S32;
static constexpr size_t O_W64 = O_W32 + S32;
static constexpr size_t SCRATCH_TOT = O_W64 + S64;

__device__ float g_scratch[SCRATCH_TOT];

// ---------------- vector helpers ----------------

__device__ __forceinline__ float4 ld4(const float* __restrict__ p) {
    return *(const float4*)p;
}
__device__ __forceinline__ void st4(float* __restrict__ p, float4 v) {
    *(float4*)p = v;
}

struct VSt {             // vectorized 7-point stencil data for 4 consecutive x cells
    float4 c;            // center [i..i+3]
    float  w, e;         // scalar x-1 (of lane 0) and x+4 (of lane 3)
    float4 s, n, b, t;   // y-1, y+1, z-1, z+1
};

// edge-clamped stencil load; bcu => -x halo face is 1.0
__device__ __forceinline__ VSt ldst(const float* __restrict__ A, int id,
                                    int i4, int j, int k, bool bcu) {
    VSt r;
    r.c = ld4(A + id);
    r.w = (i4 > 0)     ? A[id - 1] : (bcu ? 1.0f : r.c.x);
    r.e = (i4 < N - 4) ? A[id + 4] : r.c.w;
    r.s = (j > 0)      ? ld4(A + id - N)  : r.c;
    r.n = (j < N - 1)  ? ld4(A + id + N)  : r.c;
    r.b = (k > 0)      ? ld4(A + id - N2) : r.c;
    r.t = (k < N - 1)  ? ld4(A + id + N2) : r.c;
    return r;
}

__device__ __forceinline__ float4 westv(const VSt& s) {
    return make_float4(s.w, s.c.x, s.c.y, s.c.z);
}
__device__ __forceinline__ float4 eastv(const VSt& s) {
    return make_float4(s.c.y, s.c.z, s.c.w, s.e);
}
__device__ __forceinline__ float4 gradx(const VSt& s) {
    float4 w = westv(s), e = eastv(s);
    return make_float4(0.5f*(e.x-w.x), 0.5f*(e.y-w.y), 0.5f*(e.z-w.z), 0.5f*(e.w-w.w));
}
__device__ __forceinline__ float4 grady(const VSt& s) {
    return make_float4(0.5f*(s.n.x-s.s.x), 0.5f*(s.n.y-s.s.y),
                       0.5f*(s.n.z-s.s.z), 0.5f*(s.n.w-s.s.w));
}
__device__ __forceinline__ float4 gradz(const VSt& s) {
    return make_float4(0.5f*(s.t.x-s.b.x), 0.5f*(s.t.y-s.b.y),
                       0.5f*(s.t.z-s.b.z), 0.5f*(s.t.w-s.b.w));
}
__device__ __forceinline__ float4 lap4(const VSt& s) {
    float4 w = westv(s), e = eastv(s);
    return make_float4(w.x+e.x+s.s.x+s.n.x+s.b.x+s.t.x-6.f*s.c.x,
                       w.y+e.y+s.s.y+s.n.y+s.b.y+s.t.y-6.f*s.c.y,
                       w.z+e.z+s.s.z+s.n.z+s.b.z+s.t.z-6.f*s.c.z,
                       w.w+e.w+s.s.w+s.n.w+s.b.w+s.t.w-6.f*s.c.w);
}

// (base + cdt*(lap(S) - A1*dSx - A2*dSy - A3*dSz) - dt*grad) * f
__device__ __forceinline__ float4 mom_rhs(const VSt& S, float4 base,
                                          float4 A1, float4 A2, float4 A3,
                                          float4 grad, float4 f,
                                          float cdt, float dt)
{
    float4 wv = westv(S), ev = eastv(S);
    float4 out;
    const float* pw = &wv.x;   const float* pe = &ev.x;
    const float* ps = &S.s.x;  const float* pn = &S.n.x;
    const float* pb = &S.b.x;  const float* pt = &S.t.x;
    const float* pc = &S.c.x;  const float* pba = &base.x;
    const float* p1 = &A1.x;   const float* p2 = &A2.x;  const float* p3 = &A3.x;
    const float* pg = &grad.x; const float* pf = &f.x;
    float* po = &out.x;
    #pragma unroll
    for (int m = 0; m < 4; ++m) {
        float lap = pw[m]+pe[m]+ps[m]+pn[m]+pb[m]+pt[m] - 6.f*pc[m];
        float ax = 0.5f*(pe[m]-pw[m]);
        float ay = 0.5f*(pn[m]-ps[m]);
        float az = 0.5f*(pt[m]-pb[m]);
        po[m] = (pba[m] + cdt*(lap - p1[m]*ax - p2[m]*ay - p3[m]*az) - dt*pg[m]) * pf[m];
    }
    return out;
}

// ---------------- kernels ----------------

__global__ void k_solid(const float4* __restrict__ vu, const float4* __restrict__ vv,
                        const float4* __restrict__ vw, const float4* __restrict__ sg,
                        const float* __restrict__ dtp,
                        float4* __restrict__ u, float4* __restrict__ v,
                        float4* __restrict__ w, float4* __restrict__ F)
{
    int id = blockIdx.x * blockDim.x + threadIdx.x;
    float dt = dtp[0];
    float4 s = sg[id];
    float4 f;
    f.x = __fdividef(1.0f, 1.0f + dt * s.x);
    f.y = __fdividef(1.0f, 1.0f + dt * s.y);
    f.z = __fdividef(1.0f, 1.0f + dt * s.z);
    f.w = __fdividef(1.0f, 1.0f + dt * s.w);
    float4 a = vu[id]; a.x *= f.x; a.y *= f.y; a.z *= f.z; a.w *= f.w; u[id] = a;
    float4 b = vv[id]; b.x *= f.x; b.y *= f.y; b.z *= f.z; b.w *= f.w; v[id] = b;
    float4 c = vw[id]; c.x *= f.x; c.y *= f.y; c.z *= f.z; c.w *= f.w; w[id] = c;
    F[id] = f;
}

__global__ void __launch_bounds__(256)
k_predictor(const float* __restrict__ u, const float* __restrict__ v,
            const float* __restrict__ w, const float* __restrict__ p,
            const float* __restrict__ F, const float* __restrict__ dtp,
            float* __restrict__ bu, float* __restrict__ bv,
            float* __restrict__ bw)
{
    int i4 = threadIdx.x * 4;
    int j = blockIdx.y * blockDim.y + threadIdx.y;
    int k = blockIdx.z * blockDim.z + threadIdx.z;
    int id = (k * N + j) * N + i4;
    float dt = dtp[0], hdt = 0.5f * dt;

    float4 f  = ld4(F + id);
    float4 uc = ld4(u + id), vc = ld4(v + id), wc = ld4(w + id);

    VSt P = ldst(p, id, i4, j, k, false);
    float4 px = gradx(P), py = grady(P), pz = gradz(P);

    VSt S = ldst(u, id, i4, j, k, true);
    st4(bu + id, mom_rhs(S, uc, uc, vc, wc, px, f, hdt, dt));
    S = ldst(v, id, i4, j, k, false);
    st4(bv + id, mom_rhs(S, vc, uc, vc, wc, py, f, hdt, dt));
    S = ldst(w, id, i4, j, k, false);
    st4(bw + id, mom_rhs(S, wc, uc, vc, wc, pz, f, hdt, dt));
}

__global__ void __launch_bounds__(256)
k_corrector(const float* __restrict__ bu, const float* __restrict__ bv,
            const float* __restrict__ bw, const float* __restrict__ p,
            const float* __restrict__ F, const float* __restrict__ dtp,
            float* __restrict__ u, float* __restrict__ v,
            float* __restrict__ w)
{
    int i4 = threadIdx.x * 4;
    int j = blockIdx.y * blockDim.y + threadIdx.y;
    int k = blockIdx.z * blockDim.z + threadIdx.z;
    int id = (k * N + j) * N + i4;
    float dt = dtp[0];

    float4 f   = ld4(F + id);
    float4 uc  = ld4(u + id),  vc  = ld4(v + id),  wc  = ld4(w + id);
    float4 buc = ld4(bu + id), bvc = ld4(bv + id), bwc = ld4(bw + id);

    VSt P = ldst(p, id, i4, j, k, false);
    float4 px = gradx(P), py = grady(P), pz = gradz(P);

    VSt S = ldst(bu, id, i4, j, k, true);
    float4 un = mom_rhs(S, uc, buc, bvc, bwc, px, f, dt, dt);
    S = ldst(bv, id, i4, j, k, false);
    float4 vn = mom_rhs(S, vc, buc, bvc, bwc, py, f, dt, dt);
    S = ldst(bw, id, i4, j, k, false);
    float4 wn = mom_rhs(S, wc, buc, bvc, bwc, pz, f, dt, dt);

    st4(u + id, un); st4(v + id, vn); st4(w + id, wn);
}

// fused: b = -div(u,v,w)/dt  AND  r0 = lap(p) - b
__global__ void __launch_bounds__(256)
k_divres(const float* __restrict__ u, const float* __restrict__ v,
         const float* __restrict__ w, const float* __restrict__ p,
         const float* __restrict__ dtp,
         float* __restrict__ bArr, float* __restrict__ r0)
{
    int i4 = threadIdx.x * 4;
    int j = blockIdx.y * blockDim.y + threadIdx.y;
    int k = blockIdx.z * blockDim.z + threadIdx.z;
    int id = (k * N + j) * N + i4;
    float nh = -0.5f * __fdividef(1.0f, dtp[0]);

    float4 uc = ld4(u + id);
    float uw = (i4 > 0)     ? u[id - 1] : 1.0f;          // bc_u inlet
    float ue = (i4 < N - 4) ? u[id + 4] : uc.w;
    float4 wv = make_float4(uw, uc.x, uc.y, uc.z);
    float4 ev = make_float4(uc.y, uc.z, uc.w, ue);

    float4 vc = ld4(v + id);
    float4 vs = (j > 0)     ? ld4(v + id - N)  : vc;
    float4 vn = (j < N - 1) ? ld4(v + id + N)  : vc;
    float4 wcc = ld4(w + id);
    float4 wb = (k > 0)     ? ld4(w + id - N2) : wcc;
    float4 wt = (k < N - 1) ? ld4(w + id + N2) : wcc;

    float4 b;
    b.x = nh * ((ev.x - wv.x) + (vn.x - vs.x) + (wt.x - wb.x));
    b.y = nh * ((ev.y - wv.y) + (vn.y - vs.y) + (wt.y - wb.y));
    b.z = nh * ((ev.z - wv.z) + (vn.z - vs.z) + (wt.z - wb.z));
    b.w = nh * ((ev.w - wv.w) + (vn.w - vs.w) + (wt.w - wb.w));
    st4(bArr + id, b);

    VSt P = ldst(p, id, i4, j, k, false);
    float4 lp = lap4(P);
    st4(r0 + id, make_float4(lp.x - b.x, lp.y - b.y, lp.z - b.z, lp.w - b.w));
}

__global__ void __launch_bounds__(256)
k_residual(const float* __restrict__ p, const float* __restrict__ b,
           float* __restrict__ r0)
{
    int i4 = threadIdx.x * 4;
    int j = blockIdx.y * blockDim.y + threadIdx.y;
    int k = blockIdx.z * blockDim.z + threadIdx.z;
    int id = (k * N + j) * N + i4;
    VSt P = ldst(p, id, i4, j, k, false);
    float4 lp = lap4(P);
    float4 bc = ld4(b + id);
    st4(r0 + id, make_float4(lp.x - bc.x, lp.y - bc.y, lp.z - bc.z, lp.w - bc.w));
}

// two-level restrict: R0(128^3) -> R1(64^3) -> R2(32^3)
__global__ void __launch_bounds__(256)
k_restrict2(const float* __restrict__ r0, float* __restrict__ r1,
            float* __restrict__ r2)
{
    __shared__ float s1[8 * 8 * 8];
    int tid = threadIdx.x;
    int bx = blockIdx.x & 7, by = (blockIdx.x >> 3) & 7, bz = blockIdx.x >> 6;

    #pragma unroll
    for (int q = 0; q < 2; ++q) {
        int idx = tid + q * 256;
        int i = idx & 7, j = (idx >> 3) & 7, k = idx >> 6;
        int gi = bx * 8 + i, gj = by * 8 + j, gk = bz * 8 + k;   // R1 coords
        const int t = 128;
        const float* a = r0 + ((size_t)(2 * gk) * t + 2 * gj) * t + 2 * gi;
        float2 a0 = *(const float2*)a;
        float2 a1 = *(const float2*)(a + t);
        float2 a2 = *(const float2*)(a + (size_t)t * t);
        float2 a3 = *(const float2*)(a + (size_t)t * t + t);
        float v = 0.125f * (a0.x + a0.y + a1.x + a1.y + a2.x + a2.y + a3.x + a3.y);
        r1[((size_t)gk * 64 + gj) * 64 + gi] = v;
        s1[idx] = v;
    }
    __syncthreads();

    if (tid < 64) {
        int i = tid & 3, j = (tid >> 2) & 3, k = tid >> 4;
        const int t = 8;
        const float* a = s1 + ((2 * k) * t + 2 * j) * t + 2 * i;
        const float* b = a + t * t;
        float v = 0.125f * (a[0] + a[1] + a[t] + a[t + 1]
                          + b[0] + b[1] + b[t] + b[t + 1]);
        int gi = bx * 4 + i, gj = by * 4 + j, gk = bz * 4 + k;
        r2[((size_t)gk * 32 + gj) * 32 + gi] = v;
    }
}

// ---- fused MG core: 32^3 residual down to 1^3 and back up to W32 ----

__device__ __forceinline__ void restrict_stage(const float* __restrict__ src,
                                               float* __restrict__ dst,
                                               int s, int tid)
{
    int n = s * s * s;
    int t = 2 * s;
    for (int idx = tid; idx < n; idx += 1024) {
        int i = idx % s;
        int j = (idx / s) % s;
        int k = idx / (s * s);
        const float* r0 = src + ((size_t)(2 * k) * t + 2 * j) * t + 2 * i;
        const float* r1 = r0 + (size_t)t * t;
        dst[idx] = 0.125f * (r0[0] + r0[1] + r0[t] + r0[t + 1]
                           + r1[0] + r1[1] + r1[t] + r1[t + 1]);
    }
}

__device__ __forceinline__ void smooth_stage(const float* __restrict__ win,
                                             const float* __restrict__ r,
                                             float* __restrict__ out,
                                             int s, int tid, bool win_zero)
{
    int n = s * s * s;
    int t = 2 * s;
    for (int idx = tid; idx < n; idx += 1024) {
        int i = idx % s;
        int j = (idx / s) % s;
        int k = idx / (s * s);
        float nsum = 0.0f;
        if (!win_zero) {
            if (i > 0)     nsum += win[idx - 1];
            if (i < s - 1) nsum += win[idx + 1];
            if (j > 0)     nsum += win[idx - s];
            if (j < s - 1) nsum += win[idx + s];
            if (k > 0)     nsum += win[idx - s * s];
            if (k < s - 1) nsum += win[idx + s * s];
        }
        float wnew = (nsum - r[idx]) * (1.0f / 6.0f);
        size_t o = ((size_t)(2 * k) * t + 2 * j) * t + 2 * i;
        size_t o2 = o + (size_t)t * t;
        out[o] = wnew;      out[o + 1] = wnew;
        out[o + t] = wnew;  out[o + t + 1] = wnew;
        out[o2] = wnew;     out[o2 + 1] = wnew;
        out[o2 + t] = wnew; out[o2 + t + 1] = wnew;
    }
}

__global__ void __launch_bounds__(1024, 1)
k_mgcore(const float* __restrict__ R2g, float* __restrict__ W32g,
         float* __restrict__ out_r)
{
    __shared__ float sR3[4096], sR4[512], sR5[64], sR6[8], sR7[1];
    __shared__ float sW2[8], sW4[64], sW8[512], sW16[4096];
    int tid = threadIdx.x;

    restrict_stage(R2g, sR3, 16, tid); __syncthreads();
    restrict_stage(sR3, sR4, 8, tid);  __syncthreads();
    restrict_stage(sR4, sR5, 4, tid);  __syncthreads();
    restrict_stage(sR5, sR6, 2, tid);  __syncthreads();
    restrict_stage(sR6, sR7, 1, tid);  __syncthreads();
    if (tid == 0) out_r[0] = sR7[0];

    smooth_stage(nullptr, sR7, sW2, 1, tid, true);  __syncthreads();
    smooth_stage(sW2, sR6, sW4, 2, tid, false);     __syncthreads();
    smooth_stage(sW4, sR5, sW8, 4, tid, false);     __syncthreads();
    smooth_stage(sW8, sR4, sW16, 8, tid, false);    __syncthreads();
    smooth_stage(sW16, sR3, W32g, 16, tid, false);
}

// smooth+prolong grid kernel (s=32)
__global__ void k_smoothprol(const float* __restrict__ win, const float* __restrict__ r,
                             float* __restrict__ out, int s)
{
    int idx = blockIdx.x * blockDim.x + threadIdx.x;
    int n = s * s * s;
    if (idx >= n) return;
    int i = idx % s;
    int j = (idx / s) % s;
    int k = idx / (s * s);
    float nsum = 0.0f;
    if (i > 0)     nsum += win[idx - 1];
    if (i < s - 1) nsum += win[idx + 1];
    if (j > 0)     nsum += win[idx - s];
    if (j < s - 1) nsum += win[idx + s];
    if (k > 0)     nsum += win[idx - s * s];
    if (k < s - 1) nsum += win[idx + s * s];
    float wnew = (nsum - r[idx]) * (1.0f / 6.0f);
    int t = 2 * s;
    size_t o = ((size_t)(2 * k) * t + 2 * j) * t + 2 * i;
    size_t o2 = o + (size_t)t * t;
    out[o] = wnew;      out[o + 1] = wnew;
    out[o + t] = wnew;  out[o + t + 1] = wnew;
    out[o2] = wnew;     out[o2 + 1] = wnew;
    out[o2 + t] = wnew; out[o2 + t + 1] = wnew;
}

// s=64 smooth+prolong fused with pressure update (float2 on the fine grid)
__global__ void __launch_bounds__(256)
k_spp64(const float* __restrict__ win, const float* __restrict__ r,
        const float* __restrict__ pin, const float* __restrict__ r0,
        float* __restrict__ wmg, float* __restrict__ pout)
{
    const int s = 64;
    int idx = blockIdx.x * blockDim.x + threadIdx.x;
    int i = idx & 63, j = (idx >> 6) & 63, k = idx >> 12;
    float nsum = 0.0f;
    if (i > 0)     nsum += win[idx - 1];
    if (i < s - 1) nsum += win[idx + 1];
    if (j > 0)     nsum += win[idx - s];
    if (j < s - 1) nsum += win[idx + s];
    if (k > 0)     nsum += win[idx - s * s];
    if (k < s - 1) nsum += win[idx + s * s];
    float wnew = (nsum - r[idx]) * (1.0f / 6.0f);
    const int t = 128;
    size_t o = ((size_t)(2 * k) * t + 2 * j) * t + 2 * i;
    float2 wv = make_float2(wnew, wnew);
    #pragma unroll
    for (int dz = 0; dz < 2; ++dz) {
        #pragma unroll
        for (int dy = 0; dy < 2; ++dy) {
            size_t q = o + (size_t)dz * t * t + (size_t)dy * t;
            float2 pv = *(const float2*)(pin + q);
            float2 rv = *(const float2*)(r0 + q);
            *(float2*)(wmg + q) = wv;
            *(float2*)(pout + q) = make_float2(pv.x - wnew + rv.x * (1.0f/6.0f),
                                               pv.y - wnew + rv.y * (1.0f/6.0f));
        }
    }
}

__global__ void __launch_bounds__(256)
k_final(const float* __restrict__ u, const float* __restrict__ v,
        const float* __restrict__ w, const float* __restrict__ p,
        const float* __restrict__ F, const float* __restrict__ dtp,
        float* __restrict__ ou, float* __restrict__ ov,
        float* __restrict__ ow)
{
    int i4 = threadIdx.x * 4;
    int j = blockIdx.y * blockDim.y + threadIdx.y;
    int k = blockIdx.z * blockDim.z + threadIdx.z;
    int id = (k * N + j) * N + i4;
    float dt = dtp[0];

    VSt P = ldst(p, id, i4, j, k, false);
    float4 px = gradx(P), py = grady(P), pz = gradz(P);
    float4 f  = ld4(F + id);
    float4 uc = ld4(u + id), vc = ld4(v + id), wc = ld4(w + id);

    st4(ou + id, make_float4((uc.x - dt*px.x)*f.x, (uc.y - dt*px.y)*f.y,
                             (uc.z - dt*px.z)*f.z, (uc.w - dt*px.w)*f.w));
    st4(ov + id, make_float4((vc.x - dt*py.x)*f.x, (vc.y - dt*py.y)*f.y,
                             (vc.z - dt*py.z)*f.z, (vc.w - dt*py.w)*f.w));
    st4(ow + id, make_float4((wc.x - dt*pz.x)*f.x, (wc.y - dt*pz.y)*f.y,
                             (wc.z - dt*pz.z)*f.z, (wc.w - dt*pz.w)*f.w));
}

// ---------------- host ----------------

static inline dim3 g1(int n) { return dim3((unsigned)((n + 255) / 256)); }

extern "C" void kernel_launch(void* const* d_in, const int* in_sizes, int n_in,
                              void* d_out, int out_size)
{
    const float* vu  = (const float*)d_in[0];
    const float* vv  = (const float*)d_in[1];
    const float* vw  = (const float*)d_in[2];
    const float* vp  = (const float*)d_in[3];
    const float* sg  = (const float*)d_in[4];
    const float* dtp = (const float*)d_in[5];

    float* out = (float*)d_out;
    float* out_u   = out;
    float* out_v   = out + (size_t)1 * N3;
    float* out_w   = out + (size_t)2 * N3;
    float* out_p   = out + (size_t)3 * N3;
    float* out_wmg = out + (size_t)4 * N3;
    float* out_r   = out + (size_t)5 * N3;

    float* SC = nullptr;
    cudaGetSymbolAddress((void**)&SC, g_scratch);

    float* U  = SC + O_U;   float* V  = SC + O_V;   float* W  = SC + O_W;
    float* BU = SC + O_BU;  float* BV = SC + O_BV;  float* BW = SC + O_BW;
    float* B  = SC + O_B;   float* R0 = SC + O_R0;  float* F  = SC + O_F;
    float* R1 = SC + O_R1;  float* R2 = SC + O_R2;
    float* W32 = SC + O_W32; float* W64 = SC + O_W64;

    dim3 TBV(32, 4, 2), TGV(1, N / 4, N / 2);   // 4 x-elems per thread

    // momentum step
    k_solid<<<N3 / 4 / 256, 256>>>((const float4*)vu, (const float4*)vv,
                                   (const float4*)vw, (const float4*)sg, dtp,
                                   (float4*)U, (float4*)V, (float4*)W, (float4*)F);
    k_predictor<<<TGV, TBV>>>(U, V, W, vp, F, dtp, BU, BV, BW);
    k_corrector<<<TGV, TBV>>>(BU, BV, BW, vp, F, dtp, U, V, W);

    // multigrid F-cycle, 2 iterations
    for (int it = 0; it < 2; ++it) {
        if (it == 0) {
            k_divres<<<TGV, TBV>>>(U, V, W, vp, dtp, B, R0);
        } else {
            k_residual<<<TGV, TBV>>>(out_p, B, R0);
        }
        const float* pin = (it == 0) ? vp : out_p;

        k_restrict2<<<512, 256>>>(R0, R1, R2);
        k_mgcore<<<1, 1024>>>(R2, W32, out_r);
        k_smoothprol<<<g1(S32), 256>>>(W32, R2, W64, 32);
        k_spp64<<<g1(S64), 256>>>(W64, R1, pin, R0, out_wmg, out_p);
    }

    // final projection + drag
    k_final<<<TGV, TBV>>>(U, V, W, out_p, F, dtp, out_u, out_v, out_w);
}